// round 9
// baseline (speedup 1.0000x reference)
#include <cuda_runtime.h>

typedef unsigned long long u64;
typedef unsigned int u32;

#define NB 16
#define NPT 4096
#define NS 1024
#define NK 32
#define NCHUNKS 4096      /* (NB*NS)/4 centroid-chunks */
#define P0SLABS 128       /* 65536 points / 512 per slab */
#define NBLOCKS 148
#define NFPSB 8           /* FPS blocks, 2 batches each */
#define NTHR 512

// ---- shared memory layout (floats) ----
#define OFF_W1    0        /* 4096 */
#define OFF_W2    4096     /* 8192 */
#define OFF_B1    12288    /* 64 */
#define OFF_B2    12352    /* 128 */
#define OFF_W0X   12480    /* 192 */
#define OFF_GRP   12672    /* per-group regions */
#define GRP_STRIDE 10672
#define GOFF_ACT   0       /* 8448 = 64 x 132 ; group0 ACT also holds W0p+B0 during P0 */
#define GOFF_PMAX  8448    /* 2048 */
#define GOFF_IDX   10496   /* 128 ints */
#define GOFF_KKEY  10624   /* 16 u64 = 32 floats */
#define GOFF_MISC  10656   /* 8 u32 */
#define SMEM_FLOATS (OFF_GRP + 2 * GRP_STRIDE)   /* 34016 */
#define SMEMB (SMEM_FLOATS * 4)                  /* 136064 B -> 1 block/SM */
/* FPS aliases dynbuf[0..32768+128): float4 sPA[4096], float4 sPB[4096], u64 keys[64] */

// ---------------- device scratch ----------------
__device__ __align__(16) float g_P0[NB * NPT * 64];
__device__ __align__(16) float g_W0x[3 * 64];
__device__ __align__(16) float g_W0p[64 * 64];
__device__ __align__(16) float g_B0[64];
__device__ __align__(16) float g_W1[64 * 64];
__device__ __align__(16) float g_B1[64];
__device__ __align__(16) float g_W2[64 * 128];
__device__ __align__(16) float g_B2[128];
__device__ int g_prog[NB];
__device__ u32 g_chunk;
__device__ u32 g_p0chunk;
__device__ u32 g_p0fin;

// ---------------- helpers ----------------
__device__ __forceinline__ u64 ffma2(u64 a, u64 b, u64 c) {
    u64 d; asm("fma.rn.f32x2 %0, %1, %2, %3;" : "=l"(d) : "l"(a), "l"(b), "l"(c)); return d;
}
__device__ __forceinline__ u64 add2(u64 a, u64 b) {
    u64 d; asm("add.rn.f32x2 %0, %1, %2;" : "=l"(d) : "l"(a), "l"(b)); return d;
}
__device__ __forceinline__ u64 mul2(u64 a, u64 b) {
    u64 d; asm("mul.rn.f32x2 %0, %1, %2;" : "=l"(d) : "l"(a), "l"(b)); return d;
}
__device__ __forceinline__ u64 dup2(float x) {
    u64 r; asm("mov.b64 %0, {%1, %1};" : "=l"(r) : "f"(x)); return r;
}
__device__ __forceinline__ u64 pack2f(float lo, float hi) {
    u64 r; asm("mov.b64 %0, {%1, %2};" : "=l"(r) : "f"(lo), "f"(hi)); return r;
}
__device__ __forceinline__ void unpack2(u64 a, float& lo, float& hi) {
    asm("mov.b64 {%0, %1}, %2;" : "=f"(lo), "=f"(hi) : "l"(a));
}
__device__ __forceinline__ void barn(int id, int cnt) {
    asm volatile("bar.sync %0, %1;" :: "r"(id), "r"(cnt) : "memory");
}
__device__ __forceinline__ void st_release_gpu(int* p, int v) {
    asm volatile("st.release.gpu.global.s32 [%0], %1;" :: "l"(p), "r"(v) : "memory");
}
__device__ __forceinline__ int ld_acquire_gpu(const int* p) {
    int v; asm volatile("ld.acquire.gpu.global.s32 %0, [%1];" : "=r"(v) : "l"(p) : "memory"); return v;
}

extern __shared__ float dynbuf[];

// ---------------- kernel 1: fold BN into weights + reset counters ----------------
__global__ void prep_kernel(
    const float* w0, const float* cb0, const float* g0, const float* b0, const float* m0, const float* v0,
    const float* w1, const float* cb1, const float* g1, const float* b1, const float* m1, const float* v1,
    const float* w2, const float* cb2, const float* g2, const float* b2, const float* m2, const float* v2)
{
    int o = threadIdx.x;
    if (o == 0) { g_chunk = 0; g_p0chunk = 0; g_p0fin = 0; }
    if (o < NB) g_prog[o] = 0;
    if (o < 64) {
        float s0 = g0[o] / sqrtf(v0[o] + 1e-5f);
        g_B0[o] = (cb0[o] - m0[o]) * s0 + b0[o];
        for (int i = 0; i < 3; i++)  g_W0x[i * 64 + o] = w0[o * 67 + i] * s0;
        for (int c = 0; c < 64; c++) g_W0p[c * 64 + o] = w0[o * 67 + 3 + c] * s0;
        float s1 = g1[o] / sqrtf(v1[o] + 1e-5f);
        g_B1[o] = (cb1[o] - m1[o]) * s1 + b1[o];
        for (int i = 0; i < 64; i++) g_W1[i * 64 + o] = w1[o * 64 + i] * s1;
    }
    if (o < 128) {
        float s2 = g2[o] / sqrtf(v2[o] + 1e-5f);
        g_B2[o] = (cb2[o] - m2[o]) * s2 + b2[o];
        for (int i = 0; i < 64; i++) g_W2[i * 128 + o] = w2[o * 64 + i] * s2;
    }
}

// ---------------- FPS: 2 batches interleaved per block, 512 threads ----------------
__device__ void fps2_phase(const float* __restrict__ xyz, float* __restrict__ out,
                           int bA, int bB)
{
    float4* sPA = (float4*)dynbuf;               // 4096 float4
    float4* sPB = (float4*)(dynbuf + 16384);     // 4096 float4
    u64* sKA = (u64*)(dynbuf + 32768);           // [2][16]
    u64* sKB = sKA + 32;                         // [2][16]

    int t = threadIdx.x;
    const float* xa = xyz + (size_t)bA * NPT * 3;
    const float* xbp = xyz + (size_t)bB * NPT * 3;

    float ddA[8], ddB[8];
    u64 PXA[4], PYA[4], PZA[4], PXB[4], PYB[4], PZB[4];
    {
        float fxA[8], fyA[8], fzA[8], fxB[8], fyB[8], fzB[8];
#pragma unroll
        for (int j = 0; j < 8; j++) {
            int n = t + NTHR * j;
            fxA[j] = xa[n * 3 + 0];  fyA[j] = xa[n * 3 + 1];  fzA[j] = xa[n * 3 + 2];
            fxB[j] = xbp[n * 3 + 0]; fyB[j] = xbp[n * 3 + 1]; fzB[j] = xbp[n * 3 + 2];
            sPA[n] = make_float4(fxA[j], fyA[j], fzA[j], 0.f);
            sPB[n] = make_float4(fxB[j], fyB[j], fzB[j], 0.f);
            ddA[j] = 1e10f; ddB[j] = 1e10f;
        }
#pragma unroll
        for (int jp = 0; jp < 4; jp++) {
            PXA[jp] = pack2f(fxA[2 * jp], fxA[2 * jp + 1]);
            PYA[jp] = pack2f(fyA[2 * jp], fyA[2 * jp + 1]);
            PZA[jp] = pack2f(fzA[2 * jp], fzA[2 * jp + 1]);
            PXB[jp] = pack2f(fxB[2 * jp], fxB[2 * jp + 1]);
            PYB[jp] = pack2f(fyB[2 * jp], fyB[2 * jp + 1]);
            PZB[jp] = pack2f(fzB[2 * jp], fzB[2 * jp + 1]);
        }
    }
    __syncthreads();

    float4 c0A = sPA[0], c0B = sPB[0];
    float cxA = c0A.x, cyA = c0A.y, czA = c0A.z;
    float cxB = c0B.x, cyB = c0B.y, czB = c0B.z;
    if (t == 0) {
        float* oA = out + (size_t)bA * NS * 3;
        oA[0] = cxA; oA[1] = cyA; oA[2] = czA;
        float* oB = out + (size_t)bB * NS * 3;
        oB[0] = cxB; oB[1] = cyB; oB[2] = czB;
    }

    int lane = t & 31, w = t >> 5;
    for (int it = 0; it < NS - 1; it++) {
        int par = (it & 1) * 16;
        // ---- update A then B (IEEE-identical: (dx^2+dy^2)+dz^2, RN, no contraction) ----
        {
            u64 nx = dup2(-cxA), ny = dup2(-cyA), nz = dup2(-czA);
#pragma unroll
            for (int jp = 0; jp < 4; jp++) {
                u64 ax = add2(PXA[jp], nx); u64 sx = mul2(ax, ax);
                u64 ay = add2(PYA[jp], ny); u64 sy = mul2(ay, ay);
                u64 az = add2(PZA[jp], nz); u64 sz = mul2(az, az);
                u64 s = add2(add2(sx, sy), sz);
                float da, db_; unpack2(s, da, db_);
                ddA[2 * jp]     = fminf(ddA[2 * jp], da);
                ddA[2 * jp + 1] = fminf(ddA[2 * jp + 1], db_);
            }
        }
        {
            u64 nx = dup2(-cxB), ny = dup2(-cyB), nz = dup2(-czB);
#pragma unroll
            for (int jp = 0; jp < 4; jp++) {
                u64 ax = add2(PXB[jp], nx); u64 sx = mul2(ax, ax);
                u64 ay = add2(PYB[jp], ny); u64 sy = mul2(ay, ay);
                u64 az = add2(PZB[jp], nz); u64 sz = mul2(az, az);
                u64 s = add2(add2(sx, sy), sz);
                float da, db_; unpack2(s, da, db_);
                ddB[2 * jp]     = fminf(ddB[2 * jp], da);
                ddB[2 * jp + 1] = fminf(ddB[2 * jp + 1], db_);
            }
        }
        // ---- stage-1 reductions, A and B back-to-back (latencies overlap) ----
        {
            float mA = fmaxf(fmaxf(fmaxf(ddA[0], ddA[1]), fmaxf(ddA[2], ddA[3])),
                             fmaxf(fmaxf(ddA[4], ddA[5]), fmaxf(ddA[6], ddA[7])));
            float mB = fmaxf(fmaxf(fmaxf(ddB[0], ddB[1]), fmaxf(ddB[2], ddB[3])),
                             fmaxf(fmaxf(ddB[4], ddB[5]), fmaxf(ddB[6], ddB[7])));
            u32 HA = __reduce_max_sync(0xffffffffu, __float_as_uint(mA));
            u32 HB = __reduce_max_sync(0xffffffffu, __float_as_uint(mB));
            u32 ciA = 0xffffffffu, ciB = 0xffffffffu;
#pragma unroll
            for (int j = 7; j >= 0; j--) {       // high->low so min index wins
                ciA = (__float_as_uint(ddA[j]) == HA) ? (u32)(t + NTHR * j) : ciA;
                ciB = (__float_as_uint(ddB[j]) == HB) ? (u32)(t + NTHR * j) : ciB;
            }
            u32 IA = __reduce_min_sync(0xffffffffu, ciA);
            u32 IB = __reduce_min_sync(0xffffffffu, ciB);
            if (lane == 0) {
                sKA[par + w] = ((u64)HA << 32) | (u64)(u32)(~IA);
                sKB[par + w] = ((u64)HB << 32) | (u64)(u32)(~IB);
            }
        }
        __syncthreads();
        // ---- stage 2 (all warps redundantly; no extra barrier) ----
        u64 kA = (lane < 16) ? sKA[par + lane] : 0ull;
        u64 kB = (lane < 16) ? sKB[par + lane] : 0ull;
        u32 hA = (u32)(kA >> 32), hB = (u32)(kB >> 32);
        u32 HA2 = __reduce_max_sync(0xffffffffu, hA);
        u32 HB2 = __reduce_max_sync(0xffffffffu, hB);
        u32 cA2 = (hA == HA2) ? (u32)kA : 0u;
        u32 cB2 = (hB == HB2) ? (u32)kB : 0u;
        u32 LA2 = __reduce_max_sync(0xffffffffu, cA2);   // max ~idx == min idx
        u32 LB2 = __reduce_max_sync(0xffffffffu, cB2);
        int nA = (int)((~LA2) & (NPT - 1));
        int nB = (int)((~LB2) & (NPT - 1));
        float4 cA = sPA[nA], cB = sPB[nB];
        cxA = cA.x; cyA = cA.y; czA = cA.z;
        cxB = cB.x; cyB = cB.y; czB = cB.z;
        if (t == 0) {
            float* oA = out + ((size_t)bA * NS + it + 1) * 3;
            oA[0] = cxA; oA[1] = cyA; oA[2] = czA;
            float* oB = out + ((size_t)bB * NS + it + 1) * 3;
            oB[0] = cxB; oB[1] = cyB; oB[2] = czB;
            if (((it + 2) & 3) == 0) {
                st_release_gpu(&g_prog[bA], it + 2);   // release: orders prior centroid stores
                st_release_gpu(&g_prog[bB], it + 2);
            }
        }
    }
}

// ---------------- KNN for one centroid (128-thread subgroup, named barrier) ----------------
__device__ __forceinline__ void knn_one(
    const float* __restrict__ xyz, const float* __restrict__ out,
    int b, int cent, int barid, int tl, u64* sK /* 2x4 */, int* idxout)
{
    int sgc = b * NS + cent;
    float cx = __ldcg(out + (size_t)sgc * 3 + 0);
    float cy = __ldcg(out + (size_t)sgc * 3 + 1);
    float cz = __ldcg(out + (size_t)sgc * 3 + 2);
    const float* xb = xyz + (size_t)b * NPT * 3;

    float d[32];
#pragma unroll
    for (int j = 0; j < 32; j++) {
        int n = tl + 128 * j;
        float dx = __ldg(xb + n * 3 + 0) - cx;
        float dy = __ldg(xb + n * 3 + 1) - cy;
        float dz = __ldg(xb + n * 3 + 2) - cz;
        d[j] = __fadd_rn(__fadd_rn(__fmul_rn(dx, dx), __fmul_rn(dy, dy)), __fmul_rn(dz, dz));
    }
    u64 lk = ~0ull;
#pragma unroll
    for (int j = 0; j < 32; j++) {
        u64 key = ((u64)__float_as_uint(d[j]) << 32) | (u32)(tl + 128 * j);
        lk = (key < lk) ? key : lk;
    }
    int lane = tl & 31, w = tl >> 5;
    for (int r = 0; r < NK; r++) {
        u32 hi = (u32)(lk >> 32);
        u32 H = __reduce_min_sync(0xffffffffu, hi);
        u32 cand = (hi == H) ? (u32)lk : 0xffffffffu;
        u32 L = __reduce_min_sync(0xffffffffu, cand);
        if (lane == 0) sK[(r & 1) * 4 + w] = ((u64)H << 32) | (u64)L;
        barn(barid, 128);
        u64 gg = sK[(r & 1) * 4];
#pragma unroll
        for (int q = 1; q < 4; q++) { u64 k2 = sK[(r & 1) * 4 + q]; gg = (k2 < gg) ? k2 : gg; }
        if (tl == 0) idxout[r] = (int)((u32)gg);
        if (lk == gg) {
#pragma unroll
            for (int j = 0; j < 32; j++) {
                u64 key = ((u64)__float_as_uint(d[j]) << 32) | (u32)(tl + 128 * j);
                if (key == gg) d[j] = __uint_as_float(0x7f800000u);
            }
            lk = ~0ull;
#pragma unroll
            for (int j = 0; j < 32; j++) {
                u64 key = ((u64)__float_as_uint(d[j]) << 32) | (u32)(tl + 128 * j);
                lk = (key < lk) ? key : lk;
            }
        }
    }
}

// ---------------- mega kernel ----------------
__global__ __launch_bounds__(NTHR) void mega_kernel(
    const float* __restrict__ xyz, const float* __restrict__ points, float* __restrict__ out)
{
    int t = threadIdx.x;

    if (blockIdx.x < NFPSB) {
        fps2_phase(xyz, out, blockIdx.x * 2, blockIdx.x * 2 + 1);
        __syncthreads();
    }

    // ---- load weights into shared ----
    float* sW1  = dynbuf + OFF_W1;
    float* sW2  = dynbuf + OFF_W2;
    float* sB1  = dynbuf + OFF_B1;
    float* sB2  = dynbuf + OFF_B2;
    float* sW0x = dynbuf + OFF_W0X;
    float* pW0p = dynbuf + OFF_GRP;          // group0 ACT area, used only during P0
    for (int i = t; i < 4096; i += NTHR) sW1[i] = g_W1[i];
    for (int i = t; i < 8192; i += NTHR) sW2[i] = g_W2[i];
    for (int i = t; i < 4096; i += NTHR) pW0p[i] = g_W0p[i];
    if (t < 64)  sB1[t] = g_B1[t];
    if (t < 128) sB2[t] = g_B2[t];
    if (t < 192) sW0x[t] = g_W0x[t];
    if (t < 64)  pW0p[4096 + t] = g_B0[t];
    __syncthreads();

    // ---- P0: work-stolen slabs of 512 points (whole block) ----
    {
        volatile u32* sMisc0 = (volatile u32*)(dynbuf + OFF_GRP + GOFF_MISC);
        for (;;) {
            if (t == 0) sMisc0[1] = atomicAdd(&g_p0chunk, 1);
            __syncthreads();
            u32 slab = sMisc0[1];
            if (slab >= P0SLABS) break;
            int pid = (int)slab * NTHR + t;
            u64 acc[32];
            const u64* bb = (const u64*)(pW0p + 4096);
#pragma unroll
            for (int q = 0; q < 32; q++) acc[q] = bb[q];
            const float4* prr = (const float4*)(points + (size_t)pid * 64);
#pragma unroll
            for (int cc = 0; cc < 4; cc++) {
                float xr[16];
#pragma unroll
                for (int q = 0; q < 4; q++) {
                    float4 v = __ldg(prr + cc * 4 + q);
                    xr[4 * q + 0] = v.x; xr[4 * q + 1] = v.y; xr[4 * q + 2] = v.z; xr[4 * q + 3] = v.w;
                }
#pragma unroll
                for (int c = 0; c < 16; c++) {
                    u64 xi = dup2(xr[c]);
                    const ulonglong2* wr = (const ulonglong2*)(pW0p + (cc * 16 + c) * 64);
#pragma unroll
                    for (int q = 0; q < 16; q++) {
                        ulonglong2 wv = wr[q];
                        acc[2 * q]     = ffma2(xi, wv.x, acc[2 * q]);
                        acc[2 * q + 1] = ffma2(xi, wv.y, acc[2 * q + 1]);
                    }
                }
            }
            ulonglong2* op = (ulonglong2*)(g_P0 + (size_t)pid * 64);
#pragma unroll
            for (int q = 0; q < 16; q++) op[q] = make_ulonglong2(acc[2 * q], acc[2 * q + 1]);
            __threadfence();
            __syncthreads();
            if (t == 0) atomicAdd(&g_p0fin, 1);
        }
        if (t == 0) { while (ld_acquire_gpu((const int*)&g_p0fin) < P0SLABS) __nanosleep(128); }
        __syncthreads();
    }

    // ---- split into 2 independent groups of 256 ----
    int g = t >> 8, tg = t & 255;
    float* gb   = dynbuf + OFF_GRP + g * GRP_STRIDE;
    float* sAct  = gb + GOFF_ACT;
    float* sPmax = gb + GOFF_PMAX;
    int*   sIdx  = (int*)(gb + GOFF_IDX);
    u64*   sKb   = (u64*)(gb + GOFF_KKEY);
    volatile u32* sMisc = (volatile u32*)(gb + GOFF_MISC);
    int GBAR = 1 + g;

    for (;;) {
        if (tg == 0) sMisc[0] = atomicAdd(&g_chunk, 1);
        barn(GBAR, 256);
        u32 c = sMisc[0];
        if (c >= NCHUNKS) break;
        int b = (int)(c & (NB - 1));
        int s0 = (int)(c >> 4) * 4;
        if (tg == 0) { while (ld_acquire_gpu(&g_prog[b]) < s0 + 4) __nanosleep(100); }
        barn(GBAR, 256);

        // ---- KNN: 2 subgroups x 128 threads, 2 centroids each ----
        {
            int sub = tg >> 7, tl = tg & 127;
            int barid = 3 + g * 2 + sub;
            for (int ci = 0; ci < 2; ci++) {
                int cl = sub * 2 + ci;
                knn_one(xyz, out, b, s0 + cl, barid, tl, sKb + sub * 8, sIdx + cl * 32);
            }
        }
        barn(GBAR, 256);

        // ---- layer 0 -> sAct[64][132] ----
        {
            int p = tg & 127, h = tg >> 7;
            int sgp = b * NS + s0 + (p >> 5);
            int n = sIdx[p];
            float ccx = __ldcg(out + (size_t)sgp * 3 + 0);
            float ccy = __ldcg(out + (size_t)sgp * 3 + 1);
            float ccz = __ldcg(out + (size_t)sgp * 3 + 2);
            const float* xp = xyz + ((size_t)b * NPT + n) * 3;
            float gx = xp[0] - ccx, gy = xp[1] - ccy, gz = xp[2] - ccz;
            u64 dgx = dup2(gx), dgy = dup2(gy), dgz = dup2(gz);
            const ulonglong2* pr  = (const ulonglong2*)(g_P0 + ((size_t)b * NPT + n) * 64 + h * 32);
            const ulonglong2* wxa = (const ulonglong2*)(sW0x + h * 32);
            const ulonglong2* wxb = (const ulonglong2*)(sW0x + 64 + h * 32);
            const ulonglong2* wxc = (const ulonglong2*)(sW0x + 128 + h * 32);
#pragma unroll
            for (int q = 0; q < 8; q++) {
                ulonglong2 pv = pr[q];
                ulonglong2 wa = wxa[q], wb = wxb[q], wc = wxc[q];
                u64 a0 = ffma2(dgx, wa.x, pv.x); a0 = ffma2(dgy, wb.x, a0); a0 = ffma2(dgz, wc.x, a0);
                u64 a1 = ffma2(dgx, wa.y, pv.y); a1 = ffma2(dgy, wb.y, a1); a1 = ffma2(dgz, wc.y, a1);
                float v0, v1, v2, v3;
                unpack2(a0, v0, v1); unpack2(a1, v2, v3);
                int j0 = h * 32 + q * 4;
                sAct[(j0 + 0) * 132 + p] = fmaxf(v0, 0.f);
                sAct[(j0 + 1) * 132 + p] = fmaxf(v1, 0.f);
                sAct[(j0 + 2) * 132 + p] = fmaxf(v2, 0.f);
                sAct[(j0 + 3) * 132 + p] = fmaxf(v3, 0.f);
            }
        }
        barn(GBAR, 256);

        int mt = tg >> 4, nt = tg & 15;

        // ---- layer 1: thread tile 8M x 4N ----
        u64 acc[4][4];
#pragma unroll
        for (int nn = 0; nn < 4; nn++) {
            u64 bz = dup2(sB1[nt * 4 + nn]);
            acc[nn][0] = bz; acc[nn][1] = bz; acc[nn][2] = bz; acc[nn][3] = bz;
        }
        {
            const ulonglong2* A  = (const ulonglong2*)(sAct + mt * 8);
            const float4* Bw = (const float4*)(sW1 + nt * 4);
#pragma unroll
            for (int k = 0; k < 64; k++) {
                ulonglong2 a01 = A[k * 33], a23 = A[k * 33 + 1];
                float4 bw = Bw[k * 16];
                u64 b0 = dup2(bw.x), b1 = dup2(bw.y), b2 = dup2(bw.z), b3 = dup2(bw.w);
                acc[0][0] = ffma2(b0, a01.x, acc[0][0]); acc[0][1] = ffma2(b0, a01.y, acc[0][1]);
                acc[0][2] = ffma2(b0, a23.x, acc[0][2]); acc[0][3] = ffma2(b0, a23.y, acc[0][3]);
                acc[1][0] = ffma2(b1, a01.x, acc[1][0]); acc[1][1] = ffma2(b1, a01.y, acc[1][1]);
                acc[1][2] = ffma2(b1, a23.x, acc[1][2]); acc[1][3] = ffma2(b1, a23.y, acc[1][3]);
                acc[2][0] = ffma2(b2, a01.x, acc[2][0]); acc[2][1] = ffma2(b2, a01.y, acc[2][1]);
                acc[2][2] = ffma2(b2, a23.x, acc[2][2]); acc[2][3] = ffma2(b2, a23.y, acc[2][3]);
                acc[3][0] = ffma2(b3, a01.x, acc[3][0]); acc[3][1] = ffma2(b3, a01.y, acc[3][1]);
                acc[3][2] = ffma2(b3, a23.x, acc[3][2]); acc[3][3] = ffma2(b3, a23.y, acc[3][3]);
            }
        }
        barn(GBAR, 256);
#pragma unroll
        for (int nn = 0; nn < 4; nn++) {
            int row = nt * 4 + nn;
#pragma unroll
            for (int mp = 0; mp < 4; mp++) {
                float lo, hi; unpack2(acc[nn][mp], lo, hi);
                *(u64*)(sAct + row * 132 + mt * 8 + mp * 2) = pack2f(fmaxf(lo, 0.f), fmaxf(hi, 0.f));
            }
        }
        barn(GBAR, 256);

        // ---- layer 2: thread tile 8M x 8N + relu + partial max ----
        u64 acc2[8][4];
#pragma unroll
        for (int nn = 0; nn < 8; nn++) {
            u64 bz = dup2(sB2[nt * 8 + nn]);
            acc2[nn][0] = bz; acc2[nn][1] = bz; acc2[nn][2] = bz; acc2[nn][3] = bz;
        }
        {
            const ulonglong2* A = (const ulonglong2*)(sAct + mt * 8);
            const float4* Bw = (const float4*)(sW2 + nt * 8);
#pragma unroll
            for (int k = 0; k < 64; k++) {
                ulonglong2 a01 = A[k * 33], a23 = A[k * 33 + 1];
                float4 w04 = Bw[k * 32], w48 = Bw[k * 32 + 1];
                u64 b0 = dup2(w04.x), b1 = dup2(w04.y), b2 = dup2(w04.z), b3 = dup2(w04.w);
                u64 b4 = dup2(w48.x), b5 = dup2(w48.y), b6 = dup2(w48.z), b7 = dup2(w48.w);
                acc2[0][0] = ffma2(b0, a01.x, acc2[0][0]); acc2[0][1] = ffma2(b0, a01.y, acc2[0][1]);
                acc2[0][2] = ffma2(b0, a23.x, acc2[0][2]); acc2[0][3] = ffma2(b0, a23.y, acc2[0][3]);
                acc2[1][0] = ffma2(b1, a01.x, acc2[1][0]); acc2[1][1] = ffma2(b1, a01.y, acc2[1][1]);
                acc2[1][2] = ffma2(b1, a23.x, acc2[1][2]); acc2[1][3] = ffma2(b1, a23.y, acc2[1][3]);
                acc2[2][0] = ffma2(b2, a01.x, acc2[2][0]); acc2[2][1] = ffma2(b2, a01.y, acc2[2][1]);
                acc2[2][2] = ffma2(b2, a23.x, acc2[2][2]); acc2[2][3] = ffma2(b2, a23.y, acc2[2][3]);
                acc2[3][0] = ffma2(b3, a01.x, acc2[3][0]); acc2[3][1] = ffma2(b3, a01.y, acc2[3][1]);
                acc2[3][2] = ffma2(b3, a23.x, acc2[3][2]); acc2[3][3] = ffma2(b3, a23.y, acc2[3][3]);
                acc2[4][0] = ffma2(b4, a01.x, acc2[4][0]); acc2[4][1] = ffma2(b4, a01.y, acc2[4][1]);
                acc2[4][2] = ffma2(b4, a23.x, acc2[4][2]); acc2[4][3] = ffma2(b4, a23.y, acc2[4][3]);
                acc2[5][0] = ffma2(b5, a01.x, acc2[5][0]); acc2[5][1] = ffma2(b5, a01.y, acc2[5][1]);
                acc2[5][2] = ffma2(b5, a23.x, acc2[5][2]); acc2[5][3] = ffma2(b5, a23.y, acc2[5][3]);
                acc2[6][0] = ffma2(b6, a01.x, acc2[6][0]); acc2[6][1] = ffma2(b6, a01.y, acc2[6][1]);
                acc2[6][2] = ffma2(b6, a23.x, acc2[6][2]); acc2[6][3] = ffma2(b6, a23.y, acc2[6][3]);
                acc2[7][0] = ffma2(b7, a01.x, acc2[7][0]); acc2[7][1] = ffma2(b7, a01.y, acc2[7][1]);
                acc2[7][2] = ffma2(b7, a23.x, acc2[7][2]); acc2[7][3] = ffma2(b7, a23.y, acc2[7][3]);
            }
        }
#pragma unroll
        for (int nn = 0; nn < 8; nn++) {
            float mm = -1e30f;
#pragma unroll
            for (int mp = 0; mp < 4; mp++) {
                float lo, hi; unpack2(acc2[nn][mp], lo, hi);
                mm = fmaxf(mm, fmaxf(lo, hi));
            }
            sPmax[mt * 128 + nt * 8 + nn] = fmaxf(mm, 0.f);
        }
        barn(GBAR, 256);
        if (tg < 128) {
            int ch = tg;
            float4 v;
            v.x = fmaxf(fmaxf(sPmax[ 0 * 128 + ch], sPmax[ 1 * 128 + ch]),
                        fmaxf(sPmax[ 2 * 128 + ch], sPmax[ 3 * 128 + ch]));
            v.y = fmaxf(fmaxf(sPmax[ 4 * 128 + ch], sPmax[ 5 * 128 + ch]),
                        fmaxf(sPmax[ 6 * 128 + ch], sPmax[ 7 * 128 + ch]));
            v.z = fmaxf(fmaxf(sPmax[ 8 * 128 + ch], sPmax[ 9 * 128 + ch]),
                        fmaxf(sPmax[10 * 128 + ch], sPmax[11 * 128 + ch]));
            v.w = fmaxf(fmaxf(sPmax[12 * 128 + ch], sPmax[13 * 128 + ch]),
                        fmaxf(sPmax[14 * 128 + ch], sPmax[15 * 128 + ch]));
            *(float4*)(out + (size_t)NB * NS * 3 + ((size_t)(b * 128 + ch)) * NS + s0) = v;
        }
        barn(GBAR, 256);
    }
}

// ---------------- launch ----------------
extern "C" void kernel_launch(void* const* d_in, const int* in_sizes, int n_in,
                              void* d_out, int out_size)
{
    const float* xyz = (const float*)d_in[0];
    const float* points = (const float*)d_in[1];
    const float* w0 = (const float*)d_in[2];
    const float* cb0 = (const float*)d_in[3];
    const float* g0 = (const float*)d_in[4];
    const float* b0 = (const float*)d_in[5];
    const float* m0 = (const float*)d_in[6];
    const float* v0 = (const float*)d_in[7];
    const float* w1 = (const float*)d_in[8];
    const float* cb1 = (const float*)d_in[9];
    const float* g1 = (const float*)d_in[10];
    const float* b1 = (const float*)d_in[11];
    const float* m1 = (const float*)d_in[12];
    const float* v1 = (const float*)d_in[13];
    const float* w2 = (const float*)d_in[14];
    const float* cb2 = (const float*)d_in[15];
    const float* g2 = (const float*)d_in[16];
    const float* b2 = (const float*)d_in[17];
    const float* m2 = (const float*)d_in[18];
    const float* v2 = (const float*)d_in[19];
    float* out = (float*)d_out;

    cudaFuncSetAttribute(mega_kernel, cudaFuncAttributeMaxDynamicSharedMemorySize, SMEMB);

    prep_kernel<<<1, 128>>>(w0, cb0, g0, b0, m0, v0,
                            w1, cb1, g1, b1, m1, v1,
                            w2, cb2, g2, b2, m2, v2);
    mega_kernel<<<NBLOCKS, NTHR, SMEMB>>>(xyz, points, out);
}

// round 12
// speedup vs baseline: 1.6334x; 1.6334x over previous
#include <cuda_runtime.h>

typedef unsigned long long u64;
typedef unsigned int u32;

#define NB 16
#define NPT 4096
#define NS 1024
#define NK 32
#define NCHUNKS 4096      /* (NB*NS)/4 centroid-chunks */
#define P0SLABS 128       /* 65536 points / 512 per slab */
#define NBLOCKS 148
#define NTHR 512

// ---- shared memory layout (floats) ----
#define OFF_W1    0        /* 4096 */
#define OFF_W2    4096     /* 8192 */
#define OFF_B1    12288    /* 64 */
#define OFF_B2    12352    /* 128 */
#define OFF_W0X   12480    /* 192 */
#define OFF_GRP   12672    /* per-group regions */
#define GRP_STRIDE 10672
#define GOFF_ACT   0       /* 8448 = 64 x 132 ; group0 ACT also holds W0p+B0 during P0 */
#define GOFF_PMAX  8448    /* 2048 */
#define GOFF_IDX   10496   /* 128 ints */
#define GOFF_KKEY  10624   /* 16 u64 = 32 floats */
#define GOFF_MISC  10656   /* 8 u32 */
#define SMEM_FLOATS (OFF_GRP + 2 * GRP_STRIDE)   /* 34016 */
#define SMEMB (SMEM_FLOATS * 4)                  /* 136064 B -> 1 block/SM */
/* FPS aliases dynbuf[0 .. 16384+32): float4 sP[4096] + [2][16] u64 keys (weights loaded after FPS) */

// ---------------- device scratch ----------------
__device__ __align__(16) float g_P0[NB * NPT * 64];
__device__ __align__(16) float g_W0x[3 * 64];
__device__ __align__(16) float g_W0p[64 * 64];
__device__ __align__(16) float g_B0[64];
__device__ __align__(16) float g_W1[64 * 64];
__device__ __align__(16) float g_B1[64];
__device__ __align__(16) float g_W2[64 * 128];
__device__ __align__(16) float g_B2[128];
__device__ int g_prog[NB];
__device__ u32 g_chunk;
__device__ u32 g_p0chunk;
__device__ u32 g_p0fin;

// ---------------- helpers ----------------
__device__ __forceinline__ u64 ffma2(u64 a, u64 b, u64 c) {
    u64 d; asm("fma.rn.f32x2 %0, %1, %2, %3;" : "=l"(d) : "l"(a), "l"(b), "l"(c)); return d;
}
__device__ __forceinline__ u64 add2(u64 a, u64 b) {
    u64 d; asm("add.rn.f32x2 %0, %1, %2;" : "=l"(d) : "l"(a), "l"(b)); return d;
}
__device__ __forceinline__ u64 mul2(u64 a, u64 b) {
    u64 d; asm("mul.rn.f32x2 %0, %1, %2;" : "=l"(d) : "l"(a), "l"(b)); return d;
}
__device__ __forceinline__ u64 dup2(float x) {
    u64 r; asm("mov.b64 %0, {%1, %1};" : "=l"(r) : "f"(x)); return r;
}
__device__ __forceinline__ u64 pack2f(float lo, float hi) {
    u64 r; asm("mov.b64 %0, {%1, %2};" : "=l"(r) : "f"(lo), "f"(hi)); return r;
}
__device__ __forceinline__ void unpack2(u64 a, float& lo, float& hi) {
    asm("mov.b64 {%0, %1}, %2;" : "=f"(lo), "=f"(hi) : "l"(a));
}
__device__ __forceinline__ void barn(int id, int cnt) {
    asm volatile("bar.sync %0, %1;" :: "r"(id), "r"(cnt) : "memory");
}
__device__ __forceinline__ void st_release_gpu(int* p, int v) {
    asm volatile("st.release.gpu.global.s32 [%0], %1;" :: "l"(p), "r"(v) : "memory");
}
__device__ __forceinline__ int ld_acquire_gpu(const int* p) {
    int v; asm volatile("ld.acquire.gpu.global.s32 %0, [%1];" : "=r"(v) : "l"(p) : "memory"); return v;
}

extern __shared__ float dynbuf[];

// ---------------- kernel 1: fold BN into weights + reset counters ----------------
__global__ void prep_kernel(
    const float* w0, const float* cb0, const float* g0, const float* b0, const float* m0, const float* v0,
    const float* w1, const float* cb1, const float* g1, const float* b1, const float* m1, const float* v1,
    const float* w2, const float* cb2, const float* g2, const float* b2, const float* m2, const float* v2)
{
    int o = threadIdx.x;
    if (o == 0) { g_chunk = 0; g_p0chunk = 0; g_p0fin = 0; }
    if (o < NB) g_prog[o] = 0;
    if (o < 64) {
        float s0 = g0[o] / sqrtf(v0[o] + 1e-5f);
        g_B0[o] = (cb0[o] - m0[o]) * s0 + b0[o];
        for (int i = 0; i < 3; i++)  g_W0x[i * 64 + o] = w0[o * 67 + i] * s0;
        for (int c = 0; c < 64; c++) g_W0p[c * 64 + o] = w0[o * 67 + 3 + c] * s0;
        float s1 = g1[o] / sqrtf(v1[o] + 1e-5f);
        g_B1[o] = (cb1[o] - m1[o]) * s1 + b1[o];
        for (int i = 0; i < 64; i++) g_W1[i * 64 + o] = w1[o * 64 + i] * s1;
    }
    if (o < 128) {
        float s2 = g2[o] / sqrtf(v2[o] + 1e-5f);
        g_B2[o] = (cb2[o] - m2[o]) * s2 + b2[o];
        for (int i = 0; i < 64; i++) g_W2[i * 128 + o] = w2[o * 64 + i] * s2;
    }
}

// ---------------- FPS phase (blocks 0..15), 512 threads ----------------
__device__ void fps_phase(const float* __restrict__ xyz, float* __restrict__ out_newxyz)
{
    float4* sP = (float4*)dynbuf;            // 4096 float4 = 16384 floats
    u64* sKey = (u64*)(dynbuf + 16384);      // [2][16]

    int b = blockIdx.x, t = threadIdx.x;
    const float* xb = xyz + (size_t)b * NPT * 3;

    float fx[8], fy[8], fz[8], dd[8];
#pragma unroll
    for (int j = 0; j < 8; j++) {
        int n = t + NTHR * j;
        fx[j] = xb[n * 3 + 0]; fy[j] = xb[n * 3 + 1]; fz[j] = xb[n * 3 + 2];
        sP[n] = make_float4(fx[j], fy[j], fz[j], 0.f);
        dd[j] = 1e10f;
    }
    u64 PX[4], PY[4], PZ[4];
#pragma unroll
    for (int jp = 0; jp < 4; jp++) {
        PX[jp] = pack2f(fx[2 * jp], fx[2 * jp + 1]);
        PY[jp] = pack2f(fy[2 * jp], fy[2 * jp + 1]);
        PZ[jp] = pack2f(fz[2 * jp], fz[2 * jp + 1]);
    }
    __syncthreads();

    float4 c0 = sP[0];
    float cx = c0.x, cy = c0.y, cz = c0.z;
    if (t < 3) {
        float* o0 = out_newxyz + (size_t)b * NS * 3;
        o0[t] = (t == 0) ? cx : ((t == 1) ? cy : cz);   // one predicated STG for warp 0
    }

    int lane = t & 31, w = t >> 5;
    for (int it = 0; it < NS - 1; it++) {
        u64 ncx = dup2(-cx), ncy = dup2(-cy), ncz = dup2(-cz);
        // distance update (IEEE-identical to reference: (dx^2 + dy^2) + dz^2, RN, no contraction)
#pragma unroll
        for (int jp = 0; jp < 4; jp++) {
            u64 ax = add2(PX[jp], ncx); u64 sx = mul2(ax, ax);
            u64 ay = add2(PY[jp], ncy); u64 sy = mul2(ay, ay);
            u64 az = add2(PZ[jp], ncz); u64 sz = mul2(az, az);
            u64 s = add2(add2(sx, sy), sz);
            float da, db_; unpack2(s, da, db_);
            dd[2 * jp]     = fminf(dd[2 * jp], da);
            dd[2 * jp + 1] = fminf(dd[2 * jp + 1], db_);
        }
        // fused (value, leaf) argmax tree; left-preference => min leaf index on ties
        float v; int l;
        {
            float m01 = fmaxf(dd[0], dd[1]); int i01 = (dd[1] > dd[0]) ? 1 : 0;
            float m23 = fmaxf(dd[2], dd[3]); int i23 = (dd[3] > dd[2]) ? 3 : 2;
            float m45 = fmaxf(dd[4], dd[5]); int i45 = (dd[5] > dd[4]) ? 5 : 4;
            float m67 = fmaxf(dd[6], dd[7]); int i67 = (dd[7] > dd[6]) ? 7 : 6;
            float m03 = fmaxf(m01, m23); int i03 = (m23 > m01) ? i23 : i01;
            float m47 = fmaxf(m45, m67); int i47 = (m67 > m45) ? i67 : i45;
            v = fmaxf(m03, m47); l = (m47 > m03) ? i47 : i03;
        }
        // warp argmax: distances non-negative -> bit order == float order
        u32 H = __reduce_max_sync(0xffffffffu, __float_as_uint(v));
        u32 cand = (__float_as_uint(v) == H) ? (u32)(t + NTHR * l) : 0xffffffffu;
        u32 I = __reduce_min_sync(0xffffffffu, cand);
        if (lane == 0) sKey[(it & 1) * 16 + w] = ((u64)H << 32) | (u64)(u32)(~I);
        __syncthreads();
        // stage 2: 16 warp keys, redux over lanes 0..15
        u64 k2 = (lane < 16) ? sKey[(it & 1) * 16 + lane] : 0ull;
        u32 h2 = (u32)(k2 >> 32);
        u32 H2 = __reduce_max_sync(0xffffffffu, h2);
        u32 c2 = (h2 == H2) ? (u32)k2 : 0u;
        u32 L2 = __reduce_max_sync(0xffffffffu, c2);      // max ~idx == min idx
        int n = (int)((~L2) & (NPT - 1));
        float4 cc = sP[n];
        cx = cc.x; cy = cc.y; cz = cc.z;
        if (t < 3) {
            float* oo = out_newxyz + ((size_t)b * NS + it + 1) * 3;
            oo[t] = (t == 0) ? cx : ((t == 1) ? cy : cz);
        }
        if (t == 0 && ((it + 2) & 15) == 0)
            st_release_gpu(&g_prog[b], it + 2);   // release: orders prior centroid stores
    }
}

// ---------------- KNN for one centroid (128-thread subgroup, named barrier) ----------------
__device__ __forceinline__ void knn_one(
    const float* __restrict__ xyz, const float* __restrict__ out,
    int b, int cent, int barid, int tl, u64* sK /* 2x4 */, int* idxout)
{
    int sgc = b * NS + cent;
    float cx = __ldcg(out + (size_t)sgc * 3 + 0);
    float cy = __ldcg(out + (size_t)sgc * 3 + 1);
    float cz = __ldcg(out + (size_t)sgc * 3 + 2);
    const float* xb = xyz + (size_t)b * NPT * 3;

    float d[32];
#pragma unroll
    for (int j = 0; j < 32; j++) {
        int n = tl + 128 * j;
        float dx = __ldg(xb + n * 3 + 0) - cx;
        float dy = __ldg(xb + n * 3 + 1) - cy;
        float dz = __ldg(xb + n * 3 + 2) - cz;
        d[j] = __fadd_rn(__fadd_rn(__fmul_rn(dx, dx), __fmul_rn(dy, dy)), __fmul_rn(dz, dz));
    }
    u64 lk = ~0ull;
#pragma unroll
    for (int j = 0; j < 32; j++) {
        u64 key = ((u64)__float_as_uint(d[j]) << 32) | (u32)(tl + 128 * j);
        lk = (key < lk) ? key : lk;
    }
    int lane = tl & 31, w = tl >> 5;
    for (int r = 0; r < NK; r++) {
        u32 hi = (u32)(lk >> 32);
        u32 H = __reduce_min_sync(0xffffffffu, hi);
        u32 cand = (hi == H) ? (u32)lk : 0xffffffffu;
        u32 L = __reduce_min_sync(0xffffffffu, cand);
        if (lane == 0) sK[(r & 1) * 4 + w] = ((u64)H << 32) | (u64)L;
        barn(barid, 128);
        u64 gg = sK[(r & 1) * 4];
#pragma unroll
        for (int q = 1; q < 4; q++) { u64 k2 = sK[(r & 1) * 4 + q]; gg = (k2 < gg) ? k2 : gg; }
        if (tl == 0) idxout[r] = (int)((u32)gg);
        if (lk == gg) {
#pragma unroll
            for (int j = 0; j < 32; j++) {
                u64 key = ((u64)__float_as_uint(d[j]) << 32) | (u32)(tl + 128 * j);
                if (key == gg) d[j] = __uint_as_float(0x7f800000u);
            }
            lk = ~0ull;
#pragma unroll
            for (int j = 0; j < 32; j++) {
                u64 key = ((u64)__float_as_uint(d[j]) << 32) | (u32)(tl + 128 * j);
                lk = (key < lk) ? key : lk;
            }
        }
    }
}

// ---------------- mega kernel ----------------
__global__ __launch_bounds__(NTHR) void mega_kernel(
    const float* __restrict__ xyz, const float* __restrict__ points, float* __restrict__ out)
{
    int t = threadIdx.x;

    if (blockIdx.x < NB) {
        fps_phase(xyz, out);
        __syncthreads();
    }

    // ---- load weights into shared ----
    float* sW1  = dynbuf + OFF_W1;
    float* sW2  = dynbuf + OFF_W2;
    float* sB1  = dynbuf + OFF_B1;
    float* sB2  = dynbuf + OFF_B2;
    float* sW0x = dynbuf + OFF_W0X;
    float* pW0p = dynbuf + OFF_GRP;          // group0 ACT area, used only during P0
    for (int i = t; i < 4096; i += NTHR) sW1[i] = g_W1[i];
    for (int i = t; i < 8192; i += NTHR) sW2[i] = g_W2[i];
    for (int i = t; i < 4096; i += NTHR) pW0p[i] = g_W0p[i];
    if (t < 64)  sB1[t] = g_B1[t];
    if (t < 128) sB2[t] = g_B2[t];
    if (t < 192) sW0x[t] = g_W0x[t];
    if (t < 64)  pW0p[4096 + t] = g_B0[t];
    __syncthreads();

    // ---- P0: work-stolen slabs of 512 points (whole block) ----
    {
        volatile u32* sMisc0 = (volatile u32*)(dynbuf + OFF_GRP + GOFF_MISC);
        for (;;) {
            if (t == 0) sMisc0[1] = atomicAdd(&g_p0chunk, 1);
            __syncthreads();
            u32 slab = sMisc0[1];
            if (slab >= P0SLABS) break;
            int pid = (int)slab * NTHR + t;
            u64 acc[32];
            const u64* bb = (const u64*)(pW0p + 4096);
#pragma unroll
            for (int q = 0; q < 32; q++) acc[q] = bb[q];
            const float4* prr = (const float4*)(points + (size_t)pid * 64);
#pragma unroll
            for (int cc = 0; cc < 4; cc++) {
                float xr[16];
#pragma unroll
                for (int q = 0; q < 4; q++) {
                    float4 v = __ldg(prr + cc * 4 + q);
                    xr[4 * q + 0] = v.x; xr[4 * q + 1] = v.y; xr[4 * q + 2] = v.z; xr[4 * q + 3] = v.w;
                }
#pragma unroll
                for (int c = 0; c < 16; c++) {
                    u64 xi = dup2(xr[c]);
                    const ulonglong2* wr = (const ulonglong2*)(pW0p + (cc * 16 + c) * 64);
#pragma unroll
                    for (int q = 0; q < 16; q++) {
                        ulonglong2 wv = wr[q];
                        acc[2 * q]     = ffma2(xi, wv.x, acc[2 * q]);
                        acc[2 * q + 1] = ffma2(xi, wv.y, acc[2 * q + 1]);
                    }
                }
            }
            ulonglong2* op = (ulonglong2*)(g_P0 + (size_t)pid * 64);
#pragma unroll
            for (int q = 0; q < 16; q++) op[q] = make_ulonglong2(acc[2 * q], acc[2 * q + 1]);
            __threadfence();
            __syncthreads();
            if (t == 0) atomicAdd(&g_p0fin, 1);
        }
        if (t == 0) { while (ld_acquire_gpu((const int*)&g_p0fin) < P0SLABS) __nanosleep(128); }
        __syncthreads();
    }

    // ---- split into 2 independent groups of 256 ----
    int g = t >> 8, tg = t & 255;
    float* gb   = dynbuf + OFF_GRP + g * GRP_STRIDE;
    float* sAct  = gb + GOFF_ACT;
    float* sPmax = gb + GOFF_PMAX;
    int*   sIdx  = (int*)(gb + GOFF_IDX);
    u64*   sKb   = (u64*)(gb + GOFF_KKEY);
    volatile u32* sMisc = (volatile u32*)(gb + GOFF_MISC);
    int GBAR = 1 + g;

    for (;;) {
        if (tg == 0) sMisc[0] = atomicAdd(&g_chunk, 1);
        barn(GBAR, 256);
        u32 c = sMisc[0];
        if (c >= NCHUNKS) break;
        int b = (int)(c & (NB - 1));
        int s0 = (int)(c >> 4) * 4;
        if (tg == 0) { while (ld_acquire_gpu(&g_prog[b]) < s0 + 4) __nanosleep(100); }
        barn(GBAR, 256);

        // ---- KNN: 2 subgroups x 128 threads, 2 centroids each ----
        {
            int sub = tg >> 7, tl = tg & 127;
            int barid = 3 + g * 2 + sub;
            for (int ci = 0; ci < 2; ci++) {
                int cl = sub * 2 + ci;
                knn_one(xyz, out, b, s0 + cl, barid, tl, sKb + sub * 8, sIdx + cl * 32);
            }
        }
        barn(GBAR, 256);

        // ---- layer 0 -> sAct[64][132] ----
        {
            int p = tg & 127, h = tg >> 7;
            int sgp = b * NS + s0 + (p >> 5);
            int n = sIdx[p];
            float ccx = __ldcg(out + (size_t)sgp * 3 + 0);
            float ccy = __ldcg(out + (size_t)sgp * 3 + 1);
            float ccz = __ldcg(out + (size_t)sgp * 3 + 2);
            const float* xp = xyz + ((size_t)b * NPT + n) * 3;
            float gx = xp[0] - ccx, gy = xp[1] - ccy, gz = xp[2] - ccz;
            u64 dgx = dup2(gx), dgy = dup2(gy), dgz = dup2(gz);
            const ulonglong2* pr  = (const ulonglong2*)(g_P0 + ((size_t)b * NPT + n) * 64 + h * 32);
            const ulonglong2* wxa = (const ulonglong2*)(sW0x + h * 32);
            const ulonglong2* wxb = (const ulonglong2*)(sW0x + 64 + h * 32);
            const ulonglong2* wxc = (const ulonglong2*)(sW0x + 128 + h * 32);
#pragma unroll
            for (int q = 0; q < 8; q++) {
                ulonglong2 pv = pr[q];
                ulonglong2 wa = wxa[q], wb = wxb[q], wc = wxc[q];
                u64 a0 = ffma2(dgx, wa.x, pv.x); a0 = ffma2(dgy, wb.x, a0); a0 = ffma2(dgz, wc.x, a0);
                u64 a1 = ffma2(dgx, wa.y, pv.y); a1 = ffma2(dgy, wb.y, a1); a1 = ffma2(dgz, wc.y, a1);
                float v0, v1, v2, v3;
                unpack2(a0, v0, v1); unpack2(a1, v2, v3);
                int j0 = h * 32 + q * 4;
                sAct[(j0 + 0) * 132 + p] = fmaxf(v0, 0.f);
                sAct[(j0 + 1) * 132 + p] = fmaxf(v1, 0.f);
                sAct[(j0 + 2) * 132 + p] = fmaxf(v2, 0.f);
                sAct[(j0 + 3) * 132 + p] = fmaxf(v3, 0.f);
            }
        }
        barn(GBAR, 256);

        int mt = tg >> 4, nt = tg & 15;

        // ---- layer 1: thread tile 8M x 4N ----
        u64 acc[4][4];
#pragma unroll
        for (int nn = 0; nn < 4; nn++) {
            u64 bz = dup2(sB1[nt * 4 + nn]);
            acc[nn][0] = bz; acc[nn][1] = bz; acc[nn][2] = bz; acc[nn][3] = bz;
        }
        {
            const ulonglong2* A  = (const ulonglong2*)(sAct + mt * 8);
            const float4* Bw = (const float4*)(sW1 + nt * 4);
#pragma unroll
            for (int k = 0; k < 64; k++) {
                ulonglong2 a01 = A[k * 33], a23 = A[k * 33 + 1];
                float4 bw = Bw[k * 16];
                u64 b0 = dup2(bw.x), b1 = dup2(bw.y), b2 = dup2(bw.z), b3 = dup2(bw.w);
                acc[0][0] = ffma2(b0, a01.x, acc[0][0]); acc[0][1] = ffma2(b0, a01.y, acc[0][1]);
                acc[0][2] = ffma2(b0, a23.x, acc[0][2]); acc[0][3] = ffma2(b0, a23.y, acc[0][3]);
                acc[1][0] = ffma2(b1, a01.x, acc[1][0]); acc[1][1] = ffma2(b1, a01.y, acc[1][1]);
                acc[1][2] = ffma2(b1, a23.x, acc[1][2]); acc[1][3] = ffma2(b1, a23.y, acc[1][3]);
                acc[2][0] = ffma2(b2, a01.x, acc[2][0]); acc[2][1] = ffma2(b2, a01.y, acc[2][1]);
                acc[2][2] = ffma2(b2, a23.x, acc[2][2]); acc[2][3] = ffma2(b2, a23.y, acc[2][3]);
                acc[3][0] = ffma2(b3, a01.x, acc[3][0]); acc[3][1] = ffma2(b3, a01.y, acc[3][1]);
                acc[3][2] = ffma2(b3, a23.x, acc[3][2]); acc[3][3] = ffma2(b3, a23.y, acc[3][3]);
            }
        }
        barn(GBAR, 256);
#pragma unroll
        for (int nn = 0; nn < 4; nn++) {
            int row = nt * 4 + nn;
#pragma unroll
            for (int mp = 0; mp < 4; mp++) {
                float lo, hi; unpack2(acc[nn][mp], lo, hi);
                *(u64*)(sAct + row * 132 + mt * 8 + mp * 2) = pack2f(fmaxf(lo, 0.f), fmaxf(hi, 0.f));
            }
        }
        barn(GBAR, 256);

        // ---- layer 2: thread tile 8M x 8N + relu + partial max ----
        u64 acc2[8][4];
#pragma unroll
        for (int nn = 0; nn < 8; nn++) {
            u64 bz = dup2(sB2[nt * 8 + nn]);
            acc2[nn][0] = bz; acc2[nn][1] = bz; acc2[nn][2] = bz; acc2[nn][3] = bz;
        }
        {
            const ulonglong2* A = (const ulonglong2*)(sAct + mt * 8);
            const float4* Bw = (const float4*)(sW2 + nt * 8);
#pragma unroll
            for (int k = 0; k < 64; k++) {
                ulonglong2 a01 = A[k * 33], a23 = A[k * 33 + 1];
                float4 w04 = Bw[k * 32], w48 = Bw[k * 32 + 1];
                u64 b0 = dup2(w04.x), b1 = dup2(w04.y), b2 = dup2(w04.z), b3 = dup2(w04.w);
                u64 b4 = dup2(w48.x), b5 = dup2(w48.y), b6 = dup2(w48.z), b7 = dup2(w48.w);
                acc2[0][0] = ffma2(b0, a01.x, acc2[0][0]); acc2[0][1] = ffma2(b0, a01.y, acc2[0][1]);
                acc2[0][2] = ffma2(b0, a23.x, acc2[0][2]); acc2[0][3] = ffma2(b0, a23.y, acc2[0][3]);
                acc2[1][0] = ffma2(b1, a01.x, acc2[1][0]); acc2[1][1] = ffma2(b1, a01.y, acc2[1][1]);
                acc2[1][2] = ffma2(b1, a23.x, acc2[1][2]); acc2[1][3] = ffma2(b1, a23.y, acc2[1][3]);
                acc2[2][0] = ffma2(b2, a01.x, acc2[2][0]); acc2[2][1] = ffma2(b2, a01.y, acc2[2][1]);
                acc2[2][2] = ffma2(b2, a23.x, acc2[2][2]); acc2[2][3] = ffma2(b2, a23.y, acc2[2][3]);
                acc2[3][0] = ffma2(b3, a01.x, acc2[3][0]); acc2[3][1] = ffma2(b3, a01.y, acc2[3][1]);
                acc2[3][2] = ffma2(b3, a23.x, acc2[3][2]); acc2[3][3] = ffma2(b3, a23.y, acc2[3][3]);
                acc2[4][0] = ffma2(b4, a01.x, acc2[4][0]); acc2[4][1] = ffma2(b4, a01.y, acc2[4][1]);
                acc2[4][2] = ffma2(b4, a23.x, acc2[4][2]); acc2[4][3] = ffma2(b4, a23.y, acc2[4][3]);
                acc2[5][0] = ffma2(b5, a01.x, acc2[5][0]); acc2[5][1] = ffma2(b5, a01.y, acc2[5][1]);
                acc2[5][2] = ffma2(b5, a23.x, acc2[5][2]); acc2[5][3] = ffma2(b5, a23.y, acc2[5][3]);
                acc2[6][0] = ffma2(b6, a01.x, acc2[6][0]); acc2[6][1] = ffma2(b6, a01.y, acc2[6][1]);
                acc2[6][2] = ffma2(b6, a23.x, acc2[6][2]); acc2[6][3] = ffma2(b6, a23.y, acc2[6][3]);
                acc2[7][0] = ffma2(b7, a01.x, acc2[7][0]); acc2[7][1] = ffma2(b7, a01.y, acc2[7][1]);
                acc2[7][2] = ffma2(b7, a23.x, acc2[7][2]); acc2[7][3] = ffma2(b7, a23.y, acc2[7][3]);
            }
        }
#pragma unroll
        for (int nn = 0; nn < 8; nn++) {
            float mm = -1e30f;
#pragma unroll
            for (int mp = 0; mp < 4; mp++) {
                float lo, hi; unpack2(acc2[nn][mp], lo, hi);
                mm = fmaxf(mm, fmaxf(lo, hi));
            }
            sPmax[mt * 128 + nt * 8 + nn] = fmaxf(mm, 0.f);
        }
        barn(GBAR, 256);
        if (tg < 128) {
            int ch = tg;
            float4 v;
            v.x = fmaxf(fmaxf(sPmax[ 0 * 128 + ch], sPmax[ 1 * 128 + ch]),
                        fmaxf(sPmax[ 2 * 128 + ch], sPmax[ 3 * 128 + ch]));
            v.y = fmaxf(fmaxf(sPmax[ 4 * 128 + ch], sPmax[ 5 * 128 + ch]),
                        fmaxf(sPmax[ 6 * 128 + ch], sPmax[ 7 * 128 + ch]));
            v.z = fmaxf(fmaxf(sPmax[ 8 * 128 + ch], sPmax[ 9 * 128 + ch]),
                        fmaxf(sPmax[10 * 128 + ch], sPmax[11 * 128 + ch]));
            v.w = fmaxf(fmaxf(sPmax[12 * 128 + ch], sPmax[13 * 128 + ch]),
                        fmaxf(sPmax[14 * 128 + ch], sPmax[15 * 128 + ch]));
            *(float4*)(out + (size_t)NB * NS * 3 + ((size_t)(b * 128 + ch)) * NS + s0) = v;
        }
        barn(GBAR, 256);
    }
}

// ---------------- launch ----------------
extern "C" void kernel_launch(void* const* d_in, const int* in_sizes, int n_in,
                              void* d_out, int out_size)
{
    const float* xyz = (const float*)d_in[0];
    const float* points = (const float*)d_in[1];
    const float* w0 = (const float*)d_in[2];
    const float* cb0 = (const float*)d_in[3];
    const float* g0 = (const float*)d_in[4];
    const float* b0 = (const float*)d_in[5];
    const float* m0 = (const float*)d_in[6];
    const float* v0 = (const float*)d_in[7];
    const float* w1 = (const float*)d_in[8];
    const float* cb1 = (const float*)d_in[9];
    const float* g1 = (const float*)d_in[10];
    const float* b1 = (const float*)d_in[11];
    const float* m1 = (const float*)d_in[12];
    const float* v1 = (const float*)d_in[13];
    const float* w2 = (const float*)d_in[14];
    const float* cb2 = (const float*)d_in[15];
    const float* g2 = (const float*)d_in[16];
    const float* b2 = (const float*)d_in[17];
    const float* m2 = (const float*)d_in[18];
    const float* v2 = (const float*)d_in[19];
    float* out = (float*)d_out;

    cudaFuncSetAttribute(mega_kernel, cudaFuncAttributeMaxDynamicSharedMemorySize, SMEMB);

    prep_kernel<<<1, 128>>>(w0, cb0, g0, b0, m0, v0,
                            w1, cb1, g1, b1, m1, v1,
                            w2, cb2, g2, b2, m2, v2);
    mega_kernel<<<NBLOCKS, NTHR, SMEMB>>>(xyz, points, out);
}